// round 4
// baseline (speedup 1.0000x reference)
#include <cuda_runtime.h>
#include <cuda_bf16.h>

// FilterLayer: out = irfft(rfft(x, ortho)*W, ortho) + x over last dim (L=12)
// == per-node circulant matvec: y[t] = sum_j h[n][(t-j) mod 12] * x[j],
// residual identity folded into tap d=0.
//
// R4: single kernel. R1's direct strided-LDG skeleton (DRAM-efficient: each
// warp's 3 strided LDG.128 cover 12 full lines with zero waste), plus:
//  - taps computed ONCE per thread in fp32 directly from w and held in
//    registers (grid-stride 423,936 = 207*2048 keeps node invariant),
//    removing 1/3 of L1 wavefronts and the separate build kernel.
//  - software-pipelined prefetch of the next row's 3 float4s.

#define SEQ 12
#define NODES 207
#define NFREQ 7

#define TPB 256
#define TOTAL_THREADS (NODES * 2048)          // 423,936  (== 0 mod 207)
#define NBLOCKS (TOTAL_THREADS / TPB)         // 1656

// cos/sin(m*pi/6), m = 0..11 (fp32)
__device__ __constant__ float f_COS[12] = {
    1.0f,  0.86602540378f,  0.5f,  0.0f, -0.5f, -0.86602540378f,
   -1.0f, -0.86602540378f, -0.5f,  0.0f,  0.5f,  0.86602540378f
};
__device__ __constant__ float f_SIN[12] = {
    0.0f,  0.5f,  0.86602540378f,  1.0f,  0.86602540378f,  0.5f,
    0.0f, -0.5f, -0.86602540378f, -1.0f, -0.86602540378f, -0.5f
};

__global__ void __launch_bounds__(TPB) filter_kernel(
    const float4* __restrict__ x,
    const float*  __restrict__ w,     // [207][7][2]
    float4* __restrict__ out,
    int nrows)
{
    const int tid = blockIdx.x * TPB + threadIdx.x;
    const int node = tid % NODES;     // invariant across the grid-stride

    // ---- one-time: build this node's 12 circulant taps in registers ----
    const float* wn = w + node * (NFREQ * 2);
    float w0  = __ldg(wn + 0);
    float w6r = __ldg(wn + 12);
    float wr[6], wi[6];
    #pragma unroll
    for (int k = 1; k <= 5; k++) {
        wr[k] = __ldg(wn + 2 * k);
        wi[k] = __ldg(wn + 2 * k + 1);
    }
    float h[SEQ];
    #pragma unroll
    for (int d = 0; d < SEQ; d++) {
        float acc = w0 + ((d & 1) ? -w6r : w6r);
        #pragma unroll
        for (int k = 1; k <= 5; k++) {
            const int m = (k * d) % 12;
            acc = fmaf(2.0f * wr[k], f_COS[m], acc);
            acc = fmaf(-2.0f * wi[k], f_SIN[m], acc);
        }
        h[d] = acc * (1.0f / 12.0f);
    }
    h[0] += 1.0f;   // fold residual identity

    // ---- grid-stride over rows, node-preserving; exactly 16 iterations ----
    const int iters = nrows / TOTAL_THREADS;      // 6,782,976 / 423,936 = 16
    size_t g = (size_t)tid * 3;
    const size_t gstep = (size_t)TOTAL_THREADS * 3;

    float4 a = __ldg(x + g + 0);
    float4 b = __ldg(x + g + 1);
    float4 c = __ldg(x + g + 2);

    for (int it = 0; it < iters; it++) {
        const size_t gn = g + gstep;
        float4 an, bn, cn;
        if (it + 1 < iters) {                     // prefetch next row
            an = __ldg(x + gn + 0);
            bn = __ldg(x + gn + 1);
            cn = __ldg(x + gn + 2);
        }

        const float xv[SEQ] = { a.x, a.y, a.z, a.w,
                                b.x, b.y, b.z, b.w,
                                c.x, c.y, c.z, c.w };
        float y[SEQ];
        #pragma unroll
        for (int t = 0; t < SEQ; t++) {
            float s = 0.0f;
            #pragma unroll
            for (int j = 0; j < SEQ; j++)
                s = fmaf(h[(t - j + SEQ) % SEQ], xv[j], s);  // compile-time idx
            y[t] = s;
        }

        out[g + 0] = make_float4(y[0], y[1], y[2],  y[3]);
        out[g + 1] = make_float4(y[4], y[5], y[6],  y[7]);
        out[g + 2] = make_float4(y[8], y[9], y[10], y[11]);

        a = an; b = bn; c = cn;
        g = gn;
    }
}

extern "C" void kernel_launch(void* const* d_in, const int* in_sizes, int n_in,
                              void* d_out, int out_size) {
    const float* x = (const float*)d_in[0];   // [1024,32,207,12] fp32
    const float* w = (const float*)d_in[1];   // [1,207,7,2] fp32

    const int nrows = out_size / SEQ;         // 6,782,976 = 16 * 423,936
    filter_kernel<<<NBLOCKS, TPB>>>(
        reinterpret_cast<const float4*>(x),
        w,
        reinterpret_cast<float4*>(d_out),
        nrows);
}

// round 5
// speedup vs baseline: 1.1042x; 1.1042x over previous
#include <cuda_runtime.h>
#include <cuda_bf16.h>

// FilterLayer: out = irfft(rfft(x, ortho)*W, ortho) + x over last dim (L=12)
// == per-node circulant matvec: y[t] = sum_j h[n][(t-j) mod 12] * x[j],
// residual identity folded into tap d=0.
//
// R5 = R1 skeleton (one row per thread, direct strided LDG/STG for x/out,
// which is DRAM-exact: each warp's 3 strided 128-bit ops jointly cover 12
// full lines) + taps served from shared memory. The block copies the 10KB
// tap table with coalesced float4 LDGs (96 L1 wavefronts/block vs 288 for
// R1's strided per-row tap gather), and per-thread tap reads become
// conflict-free LDS.128 on the shared crossbar instead of L1tex-queue work.

#define SEQ 12
#define NODES 207
#define NFREQ 7
#define NTAPS (NODES * SEQ)          // 2484 floats = 9936 B
#define NTAPS4 (NTAPS / 4)           // 621 float4s
#define TPB 256

__device__ __align__(16) float g_H[NTAPS];

__device__ __constant__ double c_COS[12] = {
    1.0,  0.8660254037844387,  0.5,  0.0, -0.5, -0.8660254037844387,
   -1.0, -0.8660254037844387, -0.5,  0.0,  0.5,  0.8660254037844387
};
__device__ __constant__ double c_SIN[12] = {
    0.0,  0.5,  0.8660254037844387,  1.0,  0.8660254037844387,  0.5,
    0.0, -0.5, -0.8660254037844387, -1.0, -0.8660254037844387, -0.5
};

__global__ void build_taps_kernel(const float* __restrict__ w /*[207][7][2]*/) {
    int i = blockIdx.x * blockDim.x + threadIdx.x;
    if (i >= NTAPS) return;
    int n = i / SEQ, d = i % SEQ;
    const float* wn = w + n * (NFREQ * 2);
    double acc = (double)wn[0];
    acc += ((d & 1) ? -1.0 : 1.0) * (double)wn[2 * 6];
    #pragma unroll
    for (int k = 1; k <= 5; k++) {
        int m = (k * d) % 12;
        acc += 2.0 * ((double)wn[2 * k] * c_COS[m] - (double)wn[2 * k + 1] * c_SIN[m]);
    }
    float h = (float)(acc / 12.0);
    if (d == 0) h += 1.0f;   // fold residual identity
    g_H[i] = h;
}

__global__ void __launch_bounds__(TPB) filter_apply_kernel(
    const float4* __restrict__ x, float4* __restrict__ out)
{
    __shared__ __align__(16) float s_H[NTAPS];

    const int tid = threadIdx.x;
    const int r   = blockIdx.x * TPB + tid;     // one row per thread, exact grid

    // Cooperative tap copy: coalesced float4 LDG (<=3 per thread)
    {
        const float4* gH4 = reinterpret_cast<const float4*>(g_H);
        float4* sH4 = reinterpret_cast<float4*>(s_H);
        #pragma unroll
        for (int i = tid; i < NTAPS4; i += TPB) sH4[i] = gH4[i];
    }

    // Issue the row loads before the barrier to overlap with the tap copy
    const size_t g = (size_t)r * 3;
    float4 a = __ldg(x + g + 0);
    float4 b = __ldg(x + g + 1);
    float4 c = __ldg(x + g + 2);

    __syncthreads();

    // Per-thread taps: 3x conflict-free LDS.128 (48B stride)
    const int n = r % NODES;
    const float4* hp = reinterpret_cast<const float4*>(s_H + n * SEQ);
    const float4 h0 = hp[0], h1 = hp[1], h2 = hp[2];
    const float h[SEQ] = { h0.x, h0.y, h0.z, h0.w,
                           h1.x, h1.y, h1.z, h1.w,
                           h2.x, h2.y, h2.z, h2.w };

    const float xv[SEQ] = { a.x, a.y, a.z, a.w,
                            b.x, b.y, b.z, b.w,
                            c.x, c.y, c.z, c.w };

    float y[SEQ];
    #pragma unroll
    for (int t = 0; t < SEQ; t++) {
        float s = 0.0f;
        #pragma unroll
        for (int j = 0; j < SEQ; j++)
            s = fmaf(h[(t - j + SEQ) % SEQ], xv[j], s);   // compile-time index
        y[t] = s;
    }

    out[g + 0] = make_float4(y[0], y[1], y[2],  y[3]);
    out[g + 1] = make_float4(y[4], y[5], y[6],  y[7]);
    out[g + 2] = make_float4(y[8], y[9], y[10], y[11]);
}

extern "C" void kernel_launch(void* const* d_in, const int* in_sizes, int n_in,
                              void* d_out, int out_size) {
    const float* x = (const float*)d_in[0];   // [1024,32,207,12] fp32
    const float* w = (const float*)d_in[1];   // [1,207,7,2] fp32

    build_taps_kernel<<<(NTAPS + 255) / 256, 256>>>(w);

    const int nrows = out_size / SEQ;         // 6,782,976 = 26496 * 256 exactly
    const int blocks = (nrows + TPB - 1) / TPB;
    filter_apply_kernel<<<blocks, TPB>>>(
        reinterpret_cast<const float4*>(x),
        reinterpret_cast<float4*>(d_out));
}